// round 8
// baseline (speedup 1.0000x reference)
#include <cuda_runtime.h>
#include <cuda_fp16.h>
#include <math.h>
#include <stdint.h>
#include <mma.h>

using namespace nvcuda;

#define BS    4096
#define NSLOT 32
#define D     256

// Scratch (device globals), fp16.
__device__ __align__(16) __half g_query[(size_t)NSLOT * BS * D];
__device__ __align__(16) __half g_keyp [(size_t)NSLOT * BS * D];
__device__ __align__(16) __half g_value[(size_t)NSLOT * BS * D];
__device__ __align__(16) __half g_wh   [(size_t)96 * D * D];   // fp16 weights [gemm][k][n]

// ---------------------------------------------------------------------------
// Phase 0: weights fp32 -> fp16 in proj gemm order:
//   y < 32 -> qw[y];  y >= 32 -> s=(y-32)>>1, even->kw[s], odd->vw[s]
// ---------------------------------------------------------------------------
__global__ __launch_bounds__(256) void convert_w(
    const float* __restrict__ qw,
    const float* __restrict__ kw,
    const float* __restrict__ vw)
{
    const int y = blockIdx.y;
    const float* W;
    if (y < 32) W = qw + (size_t)y * D * D;
    else {
        const int s = (y - 32) >> 1;
        W = (((y - 32) & 1) == 0 ? kw : vw) + (size_t)s * D * D;
    }
    __half* dst = g_wh + (size_t)y * D * D;
    const int i = (blockIdx.x * 256 + threadIdx.x) * 4;
    const float4 v = *(const float4*)&W[i];
    __half2 h0 = __floats2half2_rn(v.x, v.y);
    __half2 h1 = __floats2half2_rn(v.z, v.w);
    *(uint2*)&dst[i] = make_uint2(*(uint32_t*)&h0, *(uint32_t*)&h1);
}

// ---------------------------------------------------------------------------
// Phase 1: 96 GEMMs C[4096,256] = X @ W, fp16 HMMA.
// grid (2,32,96), block 256 (8 warps 2m x 4n), CTA tile 128x128.
// K-chunk 64 (4 chunks), double-buffered. B via cp.async, A via LDG+cvt+STS
// split in halves interleaved with MMA. 2 CTAs/SM.
// ---------------------------------------------------------------------------
#define A_LD     72                        // halfs: 64 + 8
#define B_LD     136                       // halfs: 128 + 8
#define A_BYTES  (128 * A_LD * 2)          // 18432
#define B_BYTES  (64 * B_LD * 2)           // 17408
#define STG_B    (A_BYTES + B_BYTES)       // 35840 bytes/stage
#define STG_H    (STG_B / 2)               // halfs/stage
#define PROJ_SMEM_BYTES (2 * STG_B)        // 71680

__device__ __forceinline__ uint32_t smem_u32(const void* p) {
    return (uint32_t)__cvta_generic_to_shared(p);
}
#define CP_ASYNC16(dst_u32, src_ptr) \
    asm volatile("cp.async.cg.shared.global [%0], [%1], 16;" :: "r"(dst_u32), "l"(src_ptr))
#define CP_COMMIT() asm volatile("cp.async.commit_group;" ::: "memory")
#define CP_WAIT0()  asm volatile("cp.async.wait_group 0;" ::: "memory")

__global__ __launch_bounds__(256, 2) void proj_wmma(
    const float* __restrict__ q,
    const float* __restrict__ k)
{
    extern __shared__ __align__(16) __half smh[];
    const uint32_t smb = smem_u32(smh);

    const int tid  = threadIdx.x;
    const int wid  = tid >> 5;
    const int lane = tid & 31;
    const int wm   = wid >> 2;             // 0..1 (64 rows)
    const int wn   = wid & 3;              // 0..3 (32 cols)
    const int n0   = blockIdx.x * 128;
    const int m0   = blockIdx.y * 128;
    const int y    = blockIdx.z;

    const float* X; __half* C;
    if (y < 32) { X = q + (size_t)y * BS * D; C = g_query + (size_t)y * BS * D; }
    else {
        const int s = (y - 32) >> 1;
        X = k + (size_t)s * BS * D;
        C = (((y - 32) & 1) == 0 ? g_keyp : g_value) + (size_t)s * BS * D;
    }
    const __half* W = g_wh + (size_t)y * D * D;

    // A staging: thread -> row = tid>>1 (128 rows), 32 floats at col (tid&1)*32
    const int a_row = tid >> 1;
    const int a_c   = (tid & 1) * 32;
    // B staging: 4 x cp.async 16B; idx -> row = idx>>4 (64 rows), col (idx&15)*8 halfs
    float4 ra[4];

    auto loadA = [&](int c, int h) {
        const float* p = &X[(size_t)(m0 + a_row) * D + c * 64 + a_c + h * 16];
#pragma unroll
        for (int i = 0; i < 4; i++) ra[i] = *(const float4*)(p + 4 * i);
    };
    auto storeA = [&](int buf, int h) {
        __half* a_s = smh + buf * STG_H;
#pragma unroll
        for (int g = 0; g < 2; g++) {
            __half2 p0 = __floats2half2_rn(ra[2 * g].x,     ra[2 * g].y);
            __half2 p1 = __floats2half2_rn(ra[2 * g].z,     ra[2 * g].w);
            __half2 p2 = __floats2half2_rn(ra[2 * g + 1].x, ra[2 * g + 1].y);
            __half2 p3 = __floats2half2_rn(ra[2 * g + 1].z, ra[2 * g + 1].w);
            uint4 u = make_uint4(*(uint32_t*)&p0, *(uint32_t*)&p1,
                                 *(uint32_t*)&p2, *(uint32_t*)&p3);
            *(uint4*)&a_s[a_row * A_LD + a_c + h * 16 + g * 8] = u;
        }
    };
    auto issueB = [&](int c, int buf) {
#pragma unroll
        for (int p = 0; p < 4; p++) {
            const int idx  = p * 256 + tid;
            const int brow = idx >> 4;
            const int bcol = (idx & 15) * 8;
            const __half* src = &W[(size_t)(c * 64 + brow) * D + n0 + bcol];
            const uint32_t dst = smb + buf * STG_B + A_BYTES + (brow * B_LD + bcol) * 2;
            CP_ASYNC16(dst, src);
        }
        CP_COMMIT();
    };

    wmma::fragment<wmma::accumulator, 16, 16, 16, float> cf[4][2];
#pragma unroll
    for (int i = 0; i < 4; i++)
#pragma unroll
        for (int j = 0; j < 2; j++) wmma::fill_fragment(cf[i][j], 0.0f);

    // MMA over two k16 slabs of a chunk half [ks0, ks0+2)
    auto mmaHalf = [&](int buf, int ks0) {
        const __half* a_s = smh + buf * STG_H;
        const __half* b_s = a_s + A_BYTES / 2;
#pragma unroll
        for (int ks = ks0; ks < ks0 + 2; ks++) {
            wmma::fragment<wmma::matrix_a, 16, 16, 16, __half, wmma::row_major> af[4];
            wmma::fragment<wmma::matrix_b, 16, 16, 16, __half, wmma::row_major> bf[2];
#pragma unroll
            for (int i = 0; i < 4; i++)
                wmma::load_matrix_sync(af[i], a_s + (wm * 64 + 16 * i) * A_LD + ks * 16, A_LD);
#pragma unroll
            for (int j = 0; j < 2; j++)
                wmma::load_matrix_sync(bf[j], b_s + (ks * 16) * B_LD + wn * 32 + 16 * j, B_LD);
#pragma unroll
            for (int i = 0; i < 4; i++)
#pragma unroll
                for (int j = 0; j < 2; j++)
                    wmma::mma_sync(cf[i][j], af[i], bf[j], cf[i][j]);
        }
    };

    // Prologue: chunk 0 into buf 0
    issueB(0, 0);
    loadA(0, 0); storeA(0, 0);
    loadA(0, 1); storeA(0, 1);
    CP_WAIT0();
    __syncthreads();

    for (int c = 0; c < 4; c++) {
        const int buf  = c & 1;
        const int nbuf = buf ^ 1;
        if (c < 3) { issueB(c + 1, nbuf); loadA(c + 1, 0); }
        mmaHalf(buf, 0);
        if (c < 3) { storeA(nbuf, 0); loadA(c + 1, 1); }
        mmaHalf(buf, 2);
        if (c < 3) { storeA(nbuf, 1); CP_WAIT0(); }
        __syncthreads();
    }

    // Epilogue: per-warp 16x20 fp32 buffer -> fp16 gmem
    float* stg = reinterpret_cast<float*>(smh) + wid * (16 * 20);
    const int er = lane >> 1;
    const int ec = (lane & 1) * 8;
#pragma unroll
    for (int i = 0; i < 4; i++) {
#pragma unroll
        for (int j = 0; j < 2; j++) {
            wmma::store_matrix_sync(stg, cf[i][j], 20, wmma::mem_row_major);
            __syncwarp();
            __half2 h[4];
#pragma unroll
            for (int t = 0; t < 4; t++)
                h[t] = __floats2half2_rn(stg[er * 20 + ec + 2 * t], stg[er * 20 + ec + 2 * t + 1]);
            *(uint4*)&C[(size_t)(m0 + wm * 64 + 16 * i + er) * D + n0 + wn * 32 + 16 * j + ec] =
                *(uint4*)&h[0];
            __syncwarp();
        }
    }
}

// ---------------------------------------------------------------------------
// Phase 2: per-batch attention on tensor cores (round-5 version, 67us).
// ---------------------------------------------------------------------------
#define QK_LD 264
#define LG_LD 36
#define P_LD  40
#define ATTN_SMEM_BYTES ((3 * 32 * QK_LD) * 2 + (2 * 32 * LG_LD) * 4 + (32 * P_LD) * 2)

__global__ __launch_bounds__(256) void attn_tc(float* __restrict__ out)
{
    extern __shared__ __align__(16) __half smem_h[];
    __half* qh = smem_h;
    __half* kh = qh + 32 * QK_LD;
    __half* vh = kh + 32 * QK_LD;
    float*  lg = (float*)(vh + 32 * QK_LD);
    __half* ph = (__half*)(lg + 2 * 32 * LG_LD);

    const int b   = blockIdx.x;
    const int tid = threadIdx.x;
    const int wid = tid >> 5;

#pragma unroll
    for (int p = 0; p < 4; p++) {
        const int idx = p * 256 + tid;
        const int n  = idx >> 5;
        const int a8 = (idx & 31) * 8;
        const size_t g = (size_t)n * BS * D + (size_t)b * D + a8;
        *(uint4*)&qh[n * QK_LD + a8] = *(const uint4*)&g_query[g];
        *(uint4*)&kh[n * QK_LD + a8] = *(const uint4*)&g_keyp[g];
        *(uint4*)&vh[n * QK_LD + a8] = *(const uint4*)&g_value[g];
    }
    __syncthreads();

    {
        const int khalf = wid >> 2;
        const int nt = (wid >> 1) & 1;
        const int mt = wid & 1;
        wmma::fragment<wmma::accumulator, 16, 16, 16, float> acc;
        wmma::fill_fragment(acc, 0.0f);
#pragma unroll
        for (int ks = 0; ks < 8; ks++) {
            const int k0 = khalf * 128 + ks * 16;
            wmma::fragment<wmma::matrix_a, 16, 16, 16, __half, wmma::row_major> af;
            wmma::fragment<wmma::matrix_b, 16, 16, 16, __half, wmma::col_major> bf;
            wmma::load_matrix_sync(af, qh + (nt * 16) * QK_LD + k0, QK_LD);
            wmma::load_matrix_sync(bf, kh + (mt * 16) * QK_LD + k0, QK_LD);
            wmma::mma_sync(acc, af, bf, acc);
        }
        wmma::store_matrix_sync(lg + khalf * 32 * LG_LD + (nt * 16) * LG_LD + mt * 16,
                                acc, LG_LD, wmma::mem_row_major);
    }
    __syncthreads();

    if (tid < 32) {
        const float* l0 = lg + tid * LG_LD;
        const float* l1 = lg + 32 * LG_LD + tid * LG_LD;
        float x[32];
        float mx = -1e30f;
#pragma unroll
        for (int m = 0; m < 32; m++) {
            x[m] = l0[m] + l1[m];
            mx = fmaxf(mx, x[m]);
        }
        float s = 0.0f;
#pragma unroll
        for (int m = 0; m < 32; m++) {
            x[m] = expf((x[m] - mx) * (1.0f / 16.0f));
            s += x[m];
        }
        const float inv = 1.0f / s;
#pragma unroll
        for (int m = 0; m < 32; m += 2)
            *(__half2*)&ph[tid * P_LD + m] = __floats2half2_rn(x[m] * inv, x[m + 1] * inv);
    }
    __syncthreads();

    {
        const int mt2 = wid >> 2;
        const int oc  = wid & 3;
        wmma::fragment<wmma::accumulator, 16, 16, 16, float> acc[4];
#pragma unroll
        for (int j = 0; j < 4; j++) wmma::fill_fragment(acc[j], 0.0f);
#pragma unroll
        for (int ks = 0; ks < 2; ks++) {
            wmma::fragment<wmma::matrix_a, 16, 16, 16, __half, wmma::row_major> af;
            wmma::load_matrix_sync(af, ph + (mt2 * 16) * P_LD + ks * 16, P_LD);
#pragma unroll
            for (int j = 0; j < 4; j++) {
                wmma::fragment<wmma::matrix_b, 16, 16, 16, __half, wmma::row_major> bf;
                wmma::load_matrix_sync(bf, vh + (ks * 16) * QK_LD + oc * 64 + j * 16, QK_LD);
                wmma::mma_sync(acc[j], af, bf, acc[j]);
            }
        }
#pragma unroll
        for (int j = 0; j < 4; j++) {
            float* dst = out + (size_t)(mt2 * 16) * BS * D + (size_t)b * D + oc * 64 + j * 16;
            wmma::store_matrix_sync(dst, acc[j], (unsigned)(BS * D), wmma::mem_row_major);
        }
    }
}

// ---------------------------------------------------------------------------
extern "C" void kernel_launch(void* const* d_in, const int* in_sizes, int n_in,
                              void* d_out, int out_size)
{
    const float* q  = (const float*)d_in[0];
    const float* k  = (const float*)d_in[1];
    const float* qw = (const float*)d_in[2];
    const float* kw = (const float*)d_in[3];
    const float* vw = (const float*)d_in[4];
    float* out = (float*)d_out;

    (void)in_sizes; (void)n_in; (void)out_size;

    dim3 gw(64, 96);
    convert_w<<<gw, 256>>>(qw, kw, vw);

    cudaFuncSetAttribute(proj_wmma, cudaFuncAttributeMaxDynamicSharedMemorySize, PROJ_SMEM_BYTES);
    dim3 grid1(2, 32, 96);
    proj_wmma<<<grid1, 256, PROJ_SMEM_BYTES>>>(q, k);

    cudaFuncSetAttribute(attn_tc, cudaFuncAttributeMaxDynamicSharedMemorySize, ATTN_SMEM_BYTES);
    attn_tc<<<BS, 256, ATTN_SMEM_BYTES>>>(out);
}

// round 9
// speedup vs baseline: 1.3565x; 1.3565x over previous
#include <cuda_runtime.h>
#include <cuda_fp16.h>
#include <math.h>
#include <stdint.h>
#include <mma.h>

using namespace nvcuda;

#define BS    4096
#define NSLOT 32
#define D     256

// Scratch (device globals), fp16.
__device__ __align__(16) __half g_query[(size_t)NSLOT * BS * D];
__device__ __align__(16) __half g_keyp [(size_t)NSLOT * BS * D];
__device__ __align__(16) __half g_value[(size_t)NSLOT * BS * D];
__device__ __align__(16) __half g_wh   [(size_t)96 * D * D];   // fp16 weights [gemm][k][n]

// ---------------------------------------------------------------------------
// Phase 0: weights fp32 -> fp16 in proj gemm order:
//   y < 32 -> qw[y];  y >= 32 -> s=(y-32)>>1, even->kw[s], odd->vw[s]
// ---------------------------------------------------------------------------
__global__ __launch_bounds__(256) void convert_w(
    const float* __restrict__ qw,
    const float* __restrict__ kw,
    const float* __restrict__ vw)
{
    const int y = blockIdx.y;
    const float* W;
    if (y < 32) W = qw + (size_t)y * D * D;
    else {
        const int s = (y - 32) >> 1;
        W = (((y - 32) & 1) == 0 ? kw : vw) + (size_t)s * D * D;
    }
    __half* dst = g_wh + (size_t)y * D * D;
    const int i = (blockIdx.x * 256 + threadIdx.x) * 4;
    const float4 v = *(const float4*)&W[i];
    __half2 h0 = __floats2half2_rn(v.x, v.y);
    __half2 h1 = __floats2half2_rn(v.z, v.w);
    *(uint2*)&dst[i] = make_uint2(*(uint32_t*)&h0, *(uint32_t*)&h1);
}

// ---------------------------------------------------------------------------
// Phase 1: 96 GEMMs C[4096,256] = X @ W, fp16 HMMA.
// Round-7 geometry: grid (2,32,96), block 256 (8 warps 2m x 4n),
// CTA tile 128x128, K-chunk 32, double-buffered, 2 CTAs/SM.
// SINGLE CHANGE vs round 7: B staged via cp.async.cg (no RF round-trip).
// ---------------------------------------------------------------------------
#define A_LD  40                          // 32 + 8
#define B_LD  136                         // 128 + 8
#define ASZ   (128 * A_LD)
#define BSZ   (32 * B_LD)
#define STG   (ASZ + BSZ)                 // 9472 halfs = 18944 B
#define PROJ_SMEM_BYTES (2 * STG * (int)sizeof(__half))   // 37888 B

__device__ __forceinline__ uint32_t smem_u32(const void* p) {
    return (uint32_t)__cvta_generic_to_shared(p);
}
#define CP_ASYNC16(dst_u32, src_ptr) \
    asm volatile("cp.async.cg.shared.global [%0], [%1], 16;" :: "r"(dst_u32), "l"(src_ptr))
#define CP_COMMIT() asm volatile("cp.async.commit_group;" ::: "memory")
#define CP_WAIT0()  asm volatile("cp.async.wait_group 0;" ::: "memory")

__global__ __launch_bounds__(256, 2) void proj_wmma(
    const float* __restrict__ q,
    const float* __restrict__ k)
{
    extern __shared__ __align__(16) __half smh[];
    const uint32_t smb = smem_u32(smh);

    const int tid  = threadIdx.x;
    const int wid  = tid >> 5;
    const int lane = tid & 31;
    const int wm   = wid >> 2;            // 0..1 (64 rows)
    const int wn   = wid & 3;             // 0..3 (32 cols)
    const int n0   = blockIdx.x * 128;
    const int m0   = blockIdx.y * 128;
    const int y    = blockIdx.z;

    const float* X; __half* C;
    if (y < 32) { X = q + (size_t)y * BS * D; C = g_query + (size_t)y * BS * D; }
    else {
        const int s = (y - 32) >> 1;
        X = k + (size_t)s * BS * D;
        C = (((y - 32) & 1) == 0 ? g_keyp : g_value) + (size_t)s * BS * D;
    }
    const __half* W = g_wh + (size_t)y * D * D;

    // A staging indices (round-7): row = tid>>3 (+32p), k offset (tid&7)*4
    const int a_row = tid >> 3;
    const int a_c4  = (tid & 7) * 4;
    // B staging (cp.async): 512 16B segs; idx -> row = idx>>4, col (idx&15)*8 halfs
    float4 ra[4];

    auto load_regs = [&](int c) {
#pragma unroll
        for (int p = 0; p < 4; p++)
            ra[p] = *(const float4*)&X[(size_t)(m0 + a_row + 32 * p) * D + c * 32 + a_c4];
    };
    auto store_smem = [&](int buf) {
        __half* a_s = smh + buf * STG;
#pragma unroll
        for (int p = 0; p < 4; p++) {
            __half2 h0 = __floats2half2_rn(ra[p].x, ra[p].y);
            __half2 h1 = __floats2half2_rn(ra[p].z, ra[p].w);
            *(__half2*)&a_s[(a_row + 32 * p) * A_LD + a_c4]     = h0;
            *(__half2*)&a_s[(a_row + 32 * p) * A_LD + a_c4 + 2] = h1;
        }
    };
    auto issueB = [&](int c, int buf) {
#pragma unroll
        for (int p = 0; p < 2; p++) {
            const int idx  = p * 256 + tid;
            const int brow = idx >> 4;            // 0..31
            const int bcol = (idx & 15) * 8;      // halfs
            const __half* src = &W[(size_t)(c * 32 + brow) * D + n0 + bcol];
            const uint32_t dst = smb + (buf * STG + ASZ + brow * B_LD + bcol) * 2;
            CP_ASYNC16(dst, src);
        }
        CP_COMMIT();
    };

    wmma::fragment<wmma::accumulator, 16, 16, 16, float> cf[4][2];
#pragma unroll
    for (int i = 0; i < 4; i++)
#pragma unroll
        for (int j = 0; j < 2; j++) wmma::fill_fragment(cf[i][j], 0.0f);

    // Prologue: chunk 0 -> buf 0
    issueB(0, 0);
    load_regs(0);
    store_smem(0);
    CP_WAIT0();
    __syncthreads();

    for (int c = 0; c < 8; c++) {
        const int buf  = c & 1;
        const int nbuf = buf ^ 1;
        if (c < 7) { issueB(c + 1, nbuf); load_regs(c + 1); }

        const __half* a_s = smh + buf * STG;
        const __half* b_s = a_s + ASZ;
#pragma unroll
        for (int ks = 0; ks < 2; ks++) {
            wmma::fragment<wmma::matrix_a, 16, 16, 16, __half, wmma::row_major> af[4];
            wmma::fragment<wmma::matrix_b, 16, 16, 16, __half, wmma::row_major> bf[2];
#pragma unroll
            for (int i = 0; i < 4; i++)
                wmma::load_matrix_sync(af[i], a_s + (wm * 64 + 16 * i) * A_LD + ks * 16, A_LD);
#pragma unroll
            for (int j = 0; j < 2; j++)
                wmma::load_matrix_sync(bf[j], b_s + (ks * 16) * B_LD + wn * 32 + 16 * j, B_LD);
#pragma unroll
            for (int i = 0; i < 4; i++)
#pragma unroll
                for (int j = 0; j < 2; j++)
                    wmma::mma_sync(cf[i][j], af[i], bf[j], cf[i][j]);
        }

        if (c < 7) { store_smem(nbuf); CP_WAIT0(); }
        __syncthreads();
    }

    // Epilogue: per-warp 16x20 fp32 buffer -> fp16 gmem
    float* stg = reinterpret_cast<float*>(smh) + wid * (16 * 20);
    const int er = lane >> 1;
    const int ec = (lane & 1) * 8;
#pragma unroll
    for (int i = 0; i < 4; i++) {
#pragma unroll
        for (int j = 0; j < 2; j++) {
            wmma::store_matrix_sync(stg, cf[i][j], 20, wmma::mem_row_major);
            __syncwarp();
            __half2 h[4];
#pragma unroll
            for (int t = 0; t < 4; t++)
                h[t] = __floats2half2_rn(stg[er * 20 + ec + 2 * t], stg[er * 20 + ec + 2 * t + 1]);
            *(uint4*)&C[(size_t)(m0 + wm * 64 + 16 * i + er) * D + n0 + wn * 32 + 16 * j + ec] =
                *(uint4*)&h[0];
            __syncwarp();
        }
    }
}

// ---------------------------------------------------------------------------
// Phase 2: per-batch attention on tensor cores (round-5 version, 67us).
// ---------------------------------------------------------------------------
#define QK_LD 264
#define LG_LD 36
#define P_LD  40
#define ATTN_SMEM_BYTES ((3 * 32 * QK_LD) * 2 + (2 * 32 * LG_LD) * 4 + (32 * P_LD) * 2)

__global__ __launch_bounds__(256) void attn_tc(float* __restrict__ out)
{
    extern __shared__ __align__(16) __half smem_h[];
    __half* qh = smem_h;
    __half* kh = qh + 32 * QK_LD;
    __half* vh = kh + 32 * QK_LD;
    float*  lg = (float*)(vh + 32 * QK_LD);
    __half* ph = (__half*)(lg + 2 * 32 * LG_LD);

    const int b   = blockIdx.x;
    const int tid = threadIdx.x;
    const int wid = tid >> 5;

#pragma unroll
    for (int p = 0; p < 4; p++) {
        const int idx = p * 256 + tid;
        const int n  = idx >> 5;
        const int a8 = (idx & 31) * 8;
        const size_t g = (size_t)n * BS * D + (size_t)b * D + a8;
        *(uint4*)&qh[n * QK_LD + a8] = *(const uint4*)&g_query[g];
        *(uint4*)&kh[n * QK_LD + a8] = *(const uint4*)&g_keyp[g];
        *(uint4*)&vh[n * QK_LD + a8] = *(const uint4*)&g_value[g];
    }
    __syncthreads();

    {
        const int khalf = wid >> 2;
        const int nt = (wid >> 1) & 1;
        const int mt = wid & 1;
        wmma::fragment<wmma::accumulator, 16, 16, 16, float> acc;
        wmma::fill_fragment(acc, 0.0f);
#pragma unroll
        for (int ks = 0; ks < 8; ks++) {
            const int k0 = khalf * 128 + ks * 16;
            wmma::fragment<wmma::matrix_a, 16, 16, 16, __half, wmma::row_major> af;
            wmma::fragment<wmma::matrix_b, 16, 16, 16, __half, wmma::col_major> bf;
            wmma::load_matrix_sync(af, qh + (nt * 16) * QK_LD + k0, QK_LD);
            wmma::load_matrix_sync(bf, kh + (mt * 16) * QK_LD + k0, QK_LD);
            wmma::mma_sync(acc, af, bf, acc);
        }
        wmma::store_matrix_sync(lg + khalf * 32 * LG_LD + (nt * 16) * LG_LD + mt * 16,
                                acc, LG_LD, wmma::mem_row_major);
    }
    __syncthreads();

    if (tid < 32) {
        const float* l0 = lg + tid * LG_LD;
        const float* l1 = lg + 32 * LG_LD + tid * LG_LD;
        float x[32];
        float mx = -1e30f;
#pragma unroll
        for (int m = 0; m < 32; m++) {
            x[m] = l0[m] + l1[m];
            mx = fmaxf(mx, x[m]);
        }
        float s = 0.0f;
#pragma unroll
        for (int m = 0; m < 32; m++) {
            x[m] = expf((x[m] - mx) * (1.0f / 16.0f));
            s += x[m];
        }
        const float inv = 1.0f / s;
#pragma unroll
        for (int m = 0; m < 32; m += 2)
            *(__half2*)&ph[tid * P_LD + m] = __floats2half2_rn(x[m] * inv, x[m + 1] * inv);
    }
    __syncthreads();

    {
        const int mt2 = wid >> 2;
        const int oc  = wid & 3;
        wmma::fragment<wmma::accumulator, 16, 16, 16, float> acc[4];
#pragma unroll
        for (int j = 0; j < 4; j++) wmma::fill_fragment(acc[j], 0.0f);
#pragma unroll
        for (int ks = 0; ks < 2; ks++) {
            wmma::fragment<wmma::matrix_a, 16, 16, 16, __half, wmma::row_major> af;
            wmma::load_matrix_sync(af, ph + (mt2 * 16) * P_LD + ks * 16, P_LD);
#pragma unroll
            for (int j = 0; j < 4; j++) {
                wmma::fragment<wmma::matrix_b, 16, 16, 16, __half, wmma::row_major> bf;
                wmma::load_matrix_sync(bf, vh + (ks * 16) * QK_LD + oc * 64 + j * 16, QK_LD);
                wmma::mma_sync(acc[j], af, bf, acc[j]);
            }
        }
#pragma unroll
        for (int j = 0; j < 4; j++) {
            float* dst = out + (size_t)(mt2 * 16) * BS * D + (size_t)b * D + oc * 64 + j * 16;
            wmma::store_matrix_sync(dst, acc[j], (unsigned)(BS * D), wmma::mem_row_major);
        }
    }
}

// ---------------------------------------------------------------------------
extern "C" void kernel_launch(void* const* d_in, const int* in_sizes, int n_in,
                              void* d_out, int out_size)
{
    const float* q  = (const float*)d_in[0];
    const float* k  = (const float*)d_in[1];
    const float* qw = (const float*)d_in[2];
    const float* kw = (const float*)d_in[3];
    const float* vw = (const float*)d_in[4];
    float* out = (float*)d_out;

    (void)in_sizes; (void)n_in; (void)out_size;

    dim3 gw(64, 96);
    convert_w<<<gw, 256>>>(qw, kw, vw);

    cudaFuncSetAttribute(proj_wmma, cudaFuncAttributeMaxDynamicSharedMemorySize, PROJ_SMEM_BYTES);
    dim3 grid1(2, 32, 96);
    proj_wmma<<<grid1, 256, PROJ_SMEM_BYTES>>>(q, k);

    cudaFuncSetAttribute(attn_tc, cudaFuncAttributeMaxDynamicSharedMemorySize, ATTN_SMEM_BYTES);
    attn_tc<<<BS, 256, ATTN_SMEM_BYTES>>>(out);
}

// round 10
// speedup vs baseline: 1.4301x; 1.0542x over previous
#include <cuda_runtime.h>
#include <cuda_fp16.h>
#include <math.h>
#include <stdint.h>
#include <mma.h>

using namespace nvcuda;

#define BS    4096
#define NSLOT 32
#define D     256

// Scratch (device globals), fp16.
__device__ __align__(16) __half g_query[(size_t)NSLOT * BS * D];
__device__ __align__(16) __half g_keyp [(size_t)NSLOT * BS * D];
__device__ __align__(16) __half g_value[(size_t)NSLOT * BS * D];
__device__ __align__(16) __half g_wh   [(size_t)96 * D * D];   // fp16 weights [gemm][k][n]

__device__ __forceinline__ uint32_t smem_u32(const void* p) {
    return (uint32_t)__cvta_generic_to_shared(p);
}
#define CP_ASYNC16(dst_u32, src_ptr) \
    asm volatile("cp.async.cg.shared.global [%0], [%1], 16;" :: "r"(dst_u32), "l"(src_ptr))
#define CP_COMMIT() asm volatile("cp.async.commit_group;" ::: "memory")
#define CP_WAIT0()  asm volatile("cp.async.wait_group 0;" ::: "memory")

// ---------------------------------------------------------------------------
// Phase 0: weights fp32 -> fp16 in proj gemm order:
//   y < 32 -> qw[y];  y >= 32 -> s=(y-32)>>1, even->kw[s], odd->vw[s]
// ---------------------------------------------------------------------------
__global__ __launch_bounds__(256) void convert_w(
    const float* __restrict__ qw,
    const float* __restrict__ kw,
    const float* __restrict__ vw)
{
    const int y = blockIdx.y;
    const float* W;
    if (y < 32) W = qw + (size_t)y * D * D;
    else {
        const int s = (y - 32) >> 1;
        W = (((y - 32) & 1) == 0 ? kw : vw) + (size_t)s * D * D;
    }
    __half* dst = g_wh + (size_t)y * D * D;
    const int i = (blockIdx.x * 256 + threadIdx.x) * 4;
    const float4 v = *(const float4*)&W[i];
    __half2 h0 = __floats2half2_rn(v.x, v.y);
    __half2 h1 = __floats2half2_rn(v.z, v.w);
    *(uint2*)&dst[i] = make_uint2(*(uint32_t*)&h0, *(uint32_t*)&h1);
}

// ---------------------------------------------------------------------------
// Phase 1: 96 GEMMs C[4096,256] = X @ W, fp16 HMMA. (round-7 proven version)
// grid (2,32,96), block 256 (8 warps 2m x 4n), CTA tile 128x128, K-chunk 32,
// double-buffered, 2 CTAs/SM.
// ---------------------------------------------------------------------------
#define A_LD  40
#define B_LD  136
#define ASZ   (128 * A_LD)
#define BSZ   (32 * B_LD)
#define STG   (ASZ + BSZ)
#define PROJ_SMEM_BYTES (2 * STG * (int)sizeof(__half))   // 37888 B

__global__ __launch_bounds__(256, 2) void proj_wmma(
    const float* __restrict__ q,
    const float* __restrict__ k)
{
    extern __shared__ __align__(16) __half smh[];

    const int tid  = threadIdx.x;
    const int wid  = tid >> 5;
    const int lane = tid & 31;
    const int wm   = wid >> 2;
    const int wn   = wid & 3;
    const int n0   = blockIdx.x * 128;
    const int m0   = blockIdx.y * 128;
    const int y    = blockIdx.z;

    const float* X; __half* C;
    if (y < 32) { X = q + (size_t)y * BS * D; C = g_query + (size_t)y * BS * D; }
    else {
        const int s = (y - 32) >> 1;
        X = k + (size_t)s * BS * D;
        C = (((y - 32) & 1) == 0 ? g_keyp : g_value) + (size_t)s * BS * D;
    }
    const __half* W = g_wh + (size_t)y * D * D;

    const int a_row = tid >> 3;
    const int a_c4  = (tid & 7) * 4;
    const int b_kk  = tid >> 4;
    const int b_n8  = (tid & 15) * 8;

    float4 ra[4];
    uint4  rb[2];

    auto load_regs = [&](int c) {
#pragma unroll
        for (int p = 0; p < 4; p++)
            ra[p] = *(const float4*)&X[(size_t)(m0 + a_row + 32 * p) * D + c * 32 + a_c4];
#pragma unroll
        for (int p = 0; p < 2; p++)
            rb[p] = *(const uint4*)&W[(size_t)(c * 32 + b_kk + 16 * p) * D + n0 + b_n8];
    };
    auto store_smem = [&](int buf) {
        __half* a_s = smh + buf * STG;
        __half* b_s = a_s + ASZ;
#pragma unroll
        for (int p = 0; p < 4; p++) {
            __half2 h0 = __floats2half2_rn(ra[p].x, ra[p].y);
            __half2 h1 = __floats2half2_rn(ra[p].z, ra[p].w);
            *(__half2*)&a_s[(a_row + 32 * p) * A_LD + a_c4]     = h0;
            *(__half2*)&a_s[(a_row + 32 * p) * A_LD + a_c4 + 2] = h1;
        }
#pragma unroll
        for (int p = 0; p < 2; p++)
            *(uint4*)&b_s[(b_kk + 16 * p) * B_LD + b_n8] = rb[p];
    };

    wmma::fragment<wmma::accumulator, 16, 16, 16, float> cf[4][2];
#pragma unroll
    for (int i = 0; i < 4; i++)
#pragma unroll
        for (int j = 0; j < 2; j++) wmma::fill_fragment(cf[i][j], 0.0f);

    load_regs(0);
    store_smem(0);
    __syncthreads();

    for (int c = 0; c < 8; c++) {
        if (c < 7) load_regs(c + 1);

        const int buf = c & 1;
        const __half* a_s = smh + buf * STG;
        const __half* b_s = a_s + ASZ;
#pragma unroll
        for (int ks = 0; ks < 2; ks++) {
            wmma::fragment<wmma::matrix_a, 16, 16, 16, __half, wmma::row_major> af[4];
            wmma::fragment<wmma::matrix_b, 16, 16, 16, __half, wmma::row_major> bf[2];
#pragma unroll
            for (int i = 0; i < 4; i++)
                wmma::load_matrix_sync(af[i], a_s + (wm * 64 + 16 * i) * A_LD + ks * 16, A_LD);
#pragma unroll
            for (int j = 0; j < 2; j++)
                wmma::load_matrix_sync(bf[j], b_s + (ks * 16) * B_LD + wn * 32 + 16 * j, B_LD);
#pragma unroll
            for (int i = 0; i < 4; i++)
#pragma unroll
                for (int j = 0; j < 2; j++)
                    wmma::mma_sync(cf[i][j], af[i], bf[j], cf[i][j]);
        }

        if (c < 7) store_smem((c + 1) & 1);
        __syncthreads();
    }

    float* stg = reinterpret_cast<float*>(smh) + wid * (16 * 20);
    const int er = lane >> 1;
    const int ec = (lane & 1) * 8;
#pragma unroll
    for (int i = 0; i < 4; i++) {
#pragma unroll
        for (int j = 0; j < 2; j++) {
            wmma::store_matrix_sync(stg, cf[i][j], 20, wmma::mem_row_major);
            __syncwarp();
            __half2 h[4];
#pragma unroll
            for (int t = 0; t < 4; t++)
                h[t] = __floats2half2_rn(stg[er * 20 + ec + 2 * t], stg[er * 20 + ec + 2 * t + 1]);
            *(uint4*)&C[(size_t)(m0 + wm * 64 + 16 * i + er) * D + n0 + wn * 32 + 16 * j + ec] =
                *(uint4*)&h[0];
            __syncwarp();
        }
    }
}

// ---------------------------------------------------------------------------
// Phase 2: per-batch attention, v2.
// grid 4096, block 256, 4 CTAs/SM (smem 56.5 KB).
// - cp.async staging
// - logits: 4 warps, full K=256 each, single fp32 lg buffer
// - softmax: 256 threads (32 rows x 8 lanes), shfl reductions
// - output: 8 warps wmma (unchanged)
// ---------------------------------------------------------------------------
#define QK_LD 264
#define LG_LD 36
#define P_LD  40
#define ATTN_SMEM_BYTES ((3 * 32 * QK_LD) * 2 + (32 * LG_LD) * 4 + (32 * P_LD) * 2)  // 57856

__global__ __launch_bounds__(256, 4) void attn_tc(float* __restrict__ out)
{
    extern __shared__ __align__(16) __half smem_h[];
    __half* qh = smem_h;                         // 32*264
    __half* kh = qh + 32 * QK_LD;                // 32*264
    __half* vh = kh + 32 * QK_LD;                // 32*264
    float*  lg = (float*)(vh + 32 * QK_LD);      // 32*36 fp32
    __half* ph = (__half*)(lg + 32 * LG_LD);     // 32*40

    const int b   = blockIdx.x;
    const int tid = threadIdx.x;
    const int wid = tid >> 5;
    const uint32_t qb = smem_u32(qh);
    const uint32_t kb = smem_u32(kh);
    const uint32_t vb = smem_u32(vh);

    // Stage q/k/v via cp.async: 1024 16B segs per tensor, 4 per thread each
#pragma unroll
    for (int p = 0; p < 4; p++) {
        const int idx = p * 256 + tid;
        const int n  = idx >> 5;
        const int a8 = (idx & 31) * 8;
        const size_t g = (size_t)n * BS * D + (size_t)b * D + a8;
        const uint32_t soff = (n * QK_LD + a8) * 2;
        CP_ASYNC16(qb + soff, &g_query[g]);
        CP_ASYNC16(kb + soff, &g_keyp[g]);
        CP_ASYNC16(vb + soff, &g_value[g]);
    }
    CP_COMMIT();
    CP_WAIT0();
    __syncthreads();

    // Logits: 4 warps, each one 16x16 tile over full K=256
    if (wid < 4) {
        const int nt = wid >> 1;
        const int mt = wid & 1;
        wmma::fragment<wmma::accumulator, 16, 16, 16, float> acc;
        wmma::fill_fragment(acc, 0.0f);
#pragma unroll
        for (int ks = 0; ks < 16; ks++) {
            wmma::fragment<wmma::matrix_a, 16, 16, 16, __half, wmma::row_major> af;
            wmma::fragment<wmma::matrix_b, 16, 16, 16, __half, wmma::col_major> bf;
            wmma::load_matrix_sync(af, qh + (nt * 16) * QK_LD + ks * 16, QK_LD);
            wmma::load_matrix_sync(bf, kh + (mt * 16) * QK_LD + ks * 16, QK_LD);
            wmma::mma_sync(acc, af, bf, acc);
        }
        wmma::store_matrix_sync(lg + (nt * 16) * LG_LD + mt * 16, acc, LG_LD,
                                wmma::mem_row_major);
    }
    __syncthreads();

    // Softmax: 32 rows x 8 lanes, 4 cols each; shfl_xor over 8-lane groups
    {
        const int row = tid >> 3;
        const int c0  = (tid & 7) * 4;
        float x0 = lg[row * LG_LD + c0 + 0];
        float x1 = lg[row * LG_LD + c0 + 1];
        float x2 = lg[row * LG_LD + c0 + 2];
        float x3 = lg[row * LG_LD + c0 + 3];
        float mx = fmaxf(fmaxf(x0, x1), fmaxf(x2, x3));
#pragma unroll
        for (int d = 1; d < 8; d <<= 1)
            mx = fmaxf(mx, __shfl_xor_sync(0xffffffffu, mx, d));
        x0 = expf((x0 - mx) * 0.0625f);
        x1 = expf((x1 - mx) * 0.0625f);
        x2 = expf((x2 - mx) * 0.0625f);
        x3 = expf((x3 - mx) * 0.0625f);
        float s = x0 + x1 + x2 + x3;
#pragma unroll
        for (int d = 1; d < 8; d <<= 1)
            s += __shfl_xor_sync(0xffffffffu, s, d);
        const float inv = 1.0f / s;
        __half2 h0 = __floats2half2_rn(x0 * inv, x1 * inv);
        __half2 h1 = __floats2half2_rn(x2 * inv, x3 * inv);
        *(uint2*)&ph[row * P_LD + c0] = make_uint2(*(uint32_t*)&h0, *(uint32_t*)&h1);
    }
    __syncthreads();

    // Output: out[n][b][o] = sum_m P[n][m] * vh[m][o]
    {
        const int mt2 = wid >> 2;
        const int oc  = wid & 3;
        wmma::fragment<wmma::accumulator, 16, 16, 16, float> acc[4];
#pragma unroll
        for (int j = 0; j < 4; j++) wmma::fill_fragment(acc[j], 0.0f);
#pragma unroll
        for (int ks = 0; ks < 2; ks++) {
            wmma::fragment<wmma::matrix_a, 16, 16, 16, __half, wmma::row_major> af;
            wmma::load_matrix_sync(af, ph + (mt2 * 16) * P_LD + ks * 16, P_LD);
#pragma unroll
            for (int j = 0; j < 4; j++) {
                wmma::fragment<wmma::matrix_b, 16, 16, 16, __half, wmma::row_major> bf;
                wmma::load_matrix_sync(bf, vh + (ks * 16) * QK_LD + oc * 64 + j * 16, QK_LD);
                wmma::mma_sync(acc[j], af, bf, acc[j]);
            }
        }
#pragma unroll
        for (int j = 0; j < 4; j++) {
            float* dst = out + (size_t)(mt2 * 16) * BS * D + (size_t)b * D + oc * 64 + j * 16;
            wmma::store_matrix_sync(dst, acc[j], (unsigned)(BS * D), wmma::mem_row_major);
        }
    }
}

// ---------------------------------------------------------------------------
extern "C" void kernel_launch(void* const* d_in, const int* in_sizes, int n_in,
                              void* d_out, int out_size)
{
    const float* q  = (const float*)d_in[0];
    const float* k  = (const float*)d_in[1];
    const float* qw = (const float*)d_in[2];
    const float* kw = (const float*)d_in[3];
    const float* vw = (const float*)d_in[4];
    float* out = (float*)d_out;

    (void)in_sizes; (void)n_in; (void)out_size;

    dim3 gw(64, 96);
    convert_w<<<gw, 256>>>(qw, kw, vw);

    cudaFuncSetAttribute(proj_wmma, cudaFuncAttributeMaxDynamicSharedMemorySize, PROJ_SMEM_BYTES);
    dim3 grid1(2, 32, 96);
    proj_wmma<<<grid1, 256, PROJ_SMEM_BYTES>>>(q, k);

    cudaFuncSetAttribute(attn_tc, cudaFuncAttributeMaxDynamicSharedMemorySize, ATTN_SMEM_BYTES);
    attn_tc<<<BS, 256, ATTN_SMEM_BYTES>>>(out);
}

// round 11
// speedup vs baseline: 1.4302x; 1.0001x over previous
#include <cuda_runtime.h>
#include <cuda_fp16.h>
#include <math.h>
#include <stdint.h>
#include <mma.h>

using namespace nvcuda;

#define BS    4096
#define NSLOT 32
#define D     256

// Packed fp16 scratch: [batch][tensor(q,k,v)][slot][dim]
//   addr(b,t,s,d) = ((b*3 + t)*NSLOT + s)*D + d = b*24576 + t*8192 + s*256 + d
#define BSTRIDE (3 * NSLOT * D)     // 24576 halfs per batch
__device__ __align__(16) __half g_scr[(size_t)BS * BSTRIDE];
__device__ __align__(16) __half g_wh [(size_t)96 * D * D];   // fp16 weights [gemm][k][n]

__device__ __forceinline__ uint32_t smem_u32(const void* p) {
    return (uint32_t)__cvta_generic_to_shared(p);
}
#define CP_ASYNC16(dst_u32, src_ptr) \
    asm volatile("cp.async.cg.shared.global [%0], [%1], 16;" :: "r"(dst_u32), "l"(src_ptr))
#define CP_COMMIT() asm volatile("cp.async.commit_group;" ::: "memory")
#define CP_WAIT0()  asm volatile("cp.async.wait_group 0;" ::: "memory")

// ---------------------------------------------------------------------------
// Phase 0: weights fp32 -> fp16 in proj gemm order:
//   y < 32 -> qw[y];  y >= 32 -> s=(y-32)>>1, even->kw[s], odd->vw[s]
// grid (16, 96), 4 x float4 per thread.
// ---------------------------------------------------------------------------
__global__ __launch_bounds__(256) void convert_w(
    const float* __restrict__ qw,
    const float* __restrict__ kw,
    const float* __restrict__ vw)
{
    const int y = blockIdx.y;
    const float* W;
    if (y < 32) W = qw + (size_t)y * D * D;
    else {
        const int s = (y - 32) >> 1;
        W = (((y - 32) & 1) == 0 ? kw : vw) + (size_t)s * D * D;
    }
    __half* dst = g_wh + (size_t)y * D * D;
    const int base = (blockIdx.x * 256 + threadIdx.x) * 4;
#pragma unroll
    for (int p = 0; p < 4; p++) {
        const int i = base + p * 16384;        // 16 blocks*256 thr*4 = 16384 floats/pass
        const float4 v = *(const float4*)&W[i];
        __half2 h0 = __floats2half2_rn(v.x, v.y);
        __half2 h1 = __floats2half2_rn(v.z, v.w);
        *(uint2*)&dst[i] = make_uint2(*(uint32_t*)&h0, *(uint32_t*)&h1);
    }
}

// ---------------------------------------------------------------------------
// Phase 1: 96 GEMMs C[4096,256] = X @ W, fp16 HMMA. (round-7 proven mainloop)
// grid (2,32,96), block 256 (8 warps 2m x 4n), CTA tile 128x128, K-chunk 32,
// double-buffered, 2 CTAs/SM. Epilogue writes packed scratch layout.
// ---------------------------------------------------------------------------
#define A_LD  40
#define B_LD  136
#define ASZ   (128 * A_LD)
#define BSZ   (32 * B_LD)
#define STG   (ASZ + BSZ)
#define PROJ_SMEM_BYTES (2 * STG * (int)sizeof(__half))   // 37888 B

__global__ __launch_bounds__(256, 2) void proj_wmma(
    const float* __restrict__ q,
    const float* __restrict__ k)
{
    extern __shared__ __align__(16) __half smh[];

    const int tid  = threadIdx.x;
    const int wid  = tid >> 5;
    const int lane = tid & 31;
    const int wm   = wid >> 2;
    const int wn   = wid & 3;
    const int n0   = blockIdx.x * 128;
    const int m0   = blockIdx.y * 128;
    const int y    = blockIdx.z;

    const float* X;
    int t_idx, s_idx;
    if (y < 32) { X = q + (size_t)y * BS * D; t_idx = 0; s_idx = y; }
    else {
        s_idx = (y - 32) >> 1;
        X = k + (size_t)s_idx * BS * D;
        t_idx = (((y - 32) & 1) == 0) ? 1 : 2;
    }
    // C(b, col) = g_scr[b*BSTRIDE + t*8192 + s*256 + col]
    __half* C = g_scr + (size_t)t_idx * (NSLOT * D) + (size_t)s_idx * D;

    const int a_row = tid >> 3;
    const int a_c4  = (tid & 7) * 4;
    const int b_kk  = tid >> 4;
    const int b_n8  = (tid & 15) * 8;

    float4 ra[4];
    uint4  rb[2];
    const __half* W = g_wh + (size_t)y * D * D;

    auto load_regs = [&](int c) {
#pragma unroll
        for (int p = 0; p < 4; p++)
            ra[p] = *(const float4*)&X[(size_t)(m0 + a_row + 32 * p) * D + c * 32 + a_c4];
#pragma unroll
        for (int p = 0; p < 2; p++)
            rb[p] = *(const uint4*)&W[(size_t)(c * 32 + b_kk + 16 * p) * D + n0 + b_n8];
    };
    auto store_smem = [&](int buf) {
        __half* a_s = smh + buf * STG;
        __half* b_s = a_s + ASZ;
#pragma unroll
        for (int p = 0; p < 4; p++) {
            __half2 h0 = __floats2half2_rn(ra[p].x, ra[p].y);
            __half2 h1 = __floats2half2_rn(ra[p].z, ra[p].w);
            *(__half2*)&a_s[(a_row + 32 * p) * A_LD + a_c4]     = h0;
            *(__half2*)&a_s[(a_row + 32 * p) * A_LD + a_c4 + 2] = h1;
        }
#pragma unroll
        for (int p = 0; p < 2; p++)
            *(uint4*)&b_s[(b_kk + 16 * p) * B_LD + b_n8] = rb[p];
    };

    wmma::fragment<wmma::accumulator, 16, 16, 16, float> cf[4][2];
#pragma unroll
    for (int i = 0; i < 4; i++)
#pragma unroll
        for (int j = 0; j < 2; j++) wmma::fill_fragment(cf[i][j], 0.0f);

    load_regs(0);
    store_smem(0);
    __syncthreads();

    for (int c = 0; c < 8; c++) {
        if (c < 7) load_regs(c + 1);

        const int buf = c & 1;
        const __half* a_s = smh + buf * STG;
        const __half* b_s = a_s + ASZ;
#pragma unroll
        for (int ks = 0; ks < 2; ks++) {
            wmma::fragment<wmma::matrix_a, 16, 16, 16, __half, wmma::row_major> af[4];
            wmma::fragment<wmma::matrix_b, 16, 16, 16, __half, wmma::row_major> bf[2];
#pragma unroll
            for (int i = 0; i < 4; i++)
                wmma::load_matrix_sync(af[i], a_s + (wm * 64 + 16 * i) * A_LD + ks * 16, A_LD);
#pragma unroll
            for (int j = 0; j < 2; j++)
                wmma::load_matrix_sync(bf[j], b_s + (ks * 16) * B_LD + wn * 32 + 16 * j, B_LD);
#pragma unroll
            for (int i = 0; i < 4; i++)
#pragma unroll
                for (int j = 0; j < 2; j++)
                    wmma::mma_sync(cf[i][j], af[i], bf[j], cf[i][j]);
        }

        if (c < 7) store_smem((c + 1) & 1);
        __syncthreads();
    }

    // Epilogue -> packed scratch
    float* stg = reinterpret_cast<float*>(smh) + wid * (16 * 20);
    const int er = lane >> 1;
    const int ec = (lane & 1) * 8;
#pragma unroll
    for (int i = 0; i < 4; i++) {
#pragma unroll
        for (int j = 0; j < 2; j++) {
            wmma::store_matrix_sync(stg, cf[i][j], 20, wmma::mem_row_major);
            __syncwarp();
            __half2 h[4];
#pragma unroll
            for (int t = 0; t < 4; t++)
                h[t] = __floats2half2_rn(stg[er * 20 + ec + 2 * t], stg[er * 20 + ec + 2 * t + 1]);
            const int brow = m0 + wm * 64 + 16 * i + er;
            *(uint4*)&C[(size_t)brow * BSTRIDE + n0 + wn * 32 + 16 * j + ec] = *(uint4*)&h[0];
            __syncwarp();
        }
    }
}

// ---------------------------------------------------------------------------
// Phase 2: per-batch attention (round-10 structure). Staging is now ONE
// contiguous 48KB block per CTA from packed scratch.
// ---------------------------------------------------------------------------
#define QK_LD 264
#define LG_LD 36
#define P_LD  40
#define ATTN_SMEM_BYTES ((3 * 32 * QK_LD) * 2 + (32 * LG_LD) * 4 + (32 * P_LD) * 2)  // 57856

__global__ __launch_bounds__(256, 4) void attn_tc(float* __restrict__ out)
{
    extern __shared__ __align__(16) __half smem_h[];
    __half* qh = smem_h;                         // t=0
    __half* kh = qh + 32 * QK_LD;                // t=1
    __half* vh = kh + 32 * QK_LD;                // t=2
    float*  lg = (float*)(vh + 32 * QK_LD);
    __half* ph = (__half*)(lg + 32 * LG_LD);

    const int b   = blockIdx.x;
    const int tid = threadIdx.x;
    const int wid = tid >> 5;
    const uint32_t sb0 = smem_u32(qh);
    const __half* src = g_scr + (size_t)b * BSTRIDE;

    // 3072 16B segs, 12/thread; t = p>>2 per unrolled group
#pragma unroll
    for (int p = 0; p < 12; p++) {
        const int idx = p * 256 + tid;           // 0..3071
        const int t   = idx >> 10;               // tensor
        const int rem = idx & 1023;
        const int n   = rem >> 5;
        const int a8  = (rem & 31) * 8;
        const uint32_t dst = sb0 + (t * 32 * QK_LD + n * QK_LD + a8) * 2;
        CP_ASYNC16(dst, src + idx * 8);
    }
    CP_COMMIT();
    CP_WAIT0();
    __syncthreads();

    // Logits: 4 warps, each a 16x16 tile over full K=256
    if (wid < 4) {
        const int nt = wid >> 1;
        const int mt = wid & 1;
        wmma::fragment<wmma::accumulator, 16, 16, 16, float> acc;
        wmma::fill_fragment(acc, 0.0f);
#pragma unroll
        for (int ks = 0; ks < 16; ks++) {
            wmma::fragment<wmma::matrix_a, 16, 16, 16, __half, wmma::row_major> af;
            wmma::fragment<wmma::matrix_b, 16, 16, 16, __half, wmma::col_major> bf;
            wmma::load_matrix_sync(af, qh + (nt * 16) * QK_LD + ks * 16, QK_LD);
            wmma::load_matrix_sync(bf, kh + (mt * 16) * QK_LD + ks * 16, QK_LD);
            wmma::mma_sync(acc, af, bf, acc);
        }
        wmma::store_matrix_sync(lg + (nt * 16) * LG_LD + mt * 16, acc, LG_LD,
                                wmma::mem_row_major);
    }
    __syncthreads();

    // Softmax: 32 rows x 8 lanes x 4 cols, shfl reductions within 8-lane groups
    {
        const int row = tid >> 3;
        const int c0  = (tid & 7) * 4;
        float x0 = lg[row * LG_LD + c0 + 0];
        float x1 = lg[row * LG_LD + c0 + 1];
        float x2 = lg[row * LG_LD + c0 + 2];
        float x3 = lg[row * LG_LD + c0 + 3];
        float mx = fmaxf(fmaxf(x0, x1), fmaxf(x2, x3));
#pragma unroll
        for (int d = 1; d < 8; d <<= 1)
            mx = fmaxf(mx, __shfl_xor_sync(0xffffffffu, mx, d));
        x0 = expf((x0 - mx) * 0.0625f);
        x1 = expf((x1 - mx) * 0.0625f);
        x2 = expf((x2 - mx) * 0.0625f);
        x3 = expf((x3 - mx) * 0.0625f);
        float s = x0 + x1 + x2 + x3;
#pragma unroll
        for (int d = 1; d < 8; d <<= 1)
            s += __shfl_xor_sync(0xffffffffu, s, d);
        const float inv = 1.0f / s;
        __half2 h0 = __floats2half2_rn(x0 * inv, x1 * inv);
        __half2 h1 = __floats2half2_rn(x2 * inv, x3 * inv);
        *(uint2*)&ph[row * P_LD + c0] = make_uint2(*(uint32_t*)&h0, *(uint32_t*)&h1);
    }
    __syncthreads();

    // Output: out[n][b][o] = sum_m P[n][m] * vh[m][o]
    {
        const int mt2 = wid >> 2;
        const int oc  = wid & 3;
        wmma::fragment<wmma::accumulator, 16, 16, 16, float> acc[4];
#pragma unroll
        for (int j = 0; j < 4; j++) wmma::fill_fragment(acc[j], 0.0f);
#pragma unroll
        for (int ks = 0; ks < 2; ks++) {
            wmma::fragment<wmma::matrix_a, 16, 16, 16, __half, wmma::row_major> af;
            wmma::load_matrix_sync(af, ph + (mt2 * 16) * P_LD + ks * 16, P_LD);
#pragma unroll
            for (int j = 0; j < 4; j++) {
                wmma::fragment<wmma::matrix_b, 16, 16, 16, __half, wmma::row_major> bf;
                wmma::load_matrix_sync(bf, vh + (ks * 16) * QK_LD + oc * 64 + j * 16, QK_LD);
                wmma::mma_sync(acc[j], af, bf, acc[j]);
            }
        }
#pragma unroll
        for (int j = 0; j < 4; j++) {
            float* dst = out + (size_t)(mt2 * 16) * BS * D + (size_t)b * D + oc * 64 + j * 16;
            wmma::store_matrix_sync(dst, acc[j], (unsigned)(BS * D), wmma::mem_row_major);
        }
    }
}

// ---------------------------------------------------------------------------
extern "C" void kernel_launch(void* const* d_in, const int* in_sizes, int n_in,
                              void* d_out, int out_size)
{
    const float* q  = (const float*)d_in[0];
    const float* k  = (const float*)d_in[1];
    const float* qw = (const float*)d_in[2];
    const float* kw = (const float*)d_in[3];
    const float* vw = (const float*)d_in[4];
    float* out = (float*)d_out;

    (void)in_sizes; (void)n_in; (void)out_size;

    dim3 gw(16, 96);
    convert_w<<<gw, 256>>>(qw, kw, vw);

    cudaFuncSetAttribute(proj_wmma, cudaFuncAttributeMaxDynamicSharedMemorySize, PROJ_SMEM_BYTES);
    dim3 grid1(2, 32, 96);
    proj_wmma<<<grid1, 256, PROJ_SMEM_BYTES>>>(q, k);

    cudaFuncSetAttribute(attn_tc, cudaFuncAttributeMaxDynamicSharedMemorySize, ATTN_SMEM_BYTES);
    attn_tc<<<BS, 256, ATTN_SMEM_BYTES>>>(out);
}